// round 15
// baseline (speedup 1.0000x reference)
#include <cuda_runtime.h>
#include <cuda_fp16.h>
#include <math.h>
#include <stdint.h>

// ---------------------------------------------------------------------------
// SHMA block: pure fp16 mma.sync GEMMs (fp32 accum), BK=64, 3-stage
// cp.async pipeline, n-major dataflow, BN1/BN2 stats fused into GEMM
// epilogues, ypre stored fp16. B=8, dim=d=512, N=4096, qkvg=2048.
// ---------------------------------------------------------------------------

#define BATCH 8
#define DIM   512
#define NPIX  4096
#define C4    2048

// ---------------- scratch (static device globals) --------------------------
__device__ __half g_ythi[67108864], g_ytlo[67108864]; // y^T (8*4096,2048)
__device__ __half g_athi[16777216], g_atlo[16777216]; // attn^T (8*4096,512)
__device__ __half g_ypreh[16777216];                  // ypre (8, 512, 4096) fp16
__device__ float g_vkp[8388608];                      // vk split-K partials
__device__ __half g_khi[16777216];                    // k [b][d][n]
__device__ __half g_vhi[16777216];                    // v [b][d][n]
__device__ __half g_qthi[16777216];                   // q^T [b][n][d]
__device__ __half g_xthi[16777216];                   // x^T [b][n][c]
__device__ __half g_othi[16777216];                   // o^T [b][n][d]
__device__ __half g_vkhi[2097152];                    // vk [b][d][e]
__device__ __half g_wqhi[1048576];                    // qkvg_w
__device__ __half g_pwhi[262144];                     // proj_w
__device__ float g_a1[2048], g_b1[2048], g_a2[512], g_b2[512];
__device__ float g_s1[2048], g_s2[2048];              // BN1 accum
__device__ float g_t1[512], g_t2[512];                // BN2 accum
__device__ float g_ksum[4096], g_z[32768];

// ---------------- helpers ---------------------------------------------------
__device__ __forceinline__ uint32_t smem_u32(const void* p) {
    uint32_t a;
    asm("{ .reg .u64 t; cvta.to.shared.u64 t, %1; cvt.u32.u64 %0, t; }"
        : "=r"(a) : "l"(p));
    return a;
}
__device__ __forceinline__ void ldsm_x4(uint32_t& r0, uint32_t& r1,
                                        uint32_t& r2, uint32_t& r3,
                                        uint32_t addr) {
    asm volatile("ldmatrix.sync.aligned.m8n8.x4.shared.b16 {%0,%1,%2,%3}, [%4];"
                 : "=r"(r0), "=r"(r1), "=r"(r2), "=r"(r3) : "r"(addr));
}
__device__ __forceinline__ void mma16816(float* c, const uint32_t* a,
                                         uint32_t b0, uint32_t b1) {
    asm volatile(
        "mma.sync.aligned.m16n8k16.row.col.f32.f16.f16.f32 "
        "{%0,%1,%2,%3}, {%4,%5,%6,%7}, {%8,%9}, {%0,%1,%2,%3};"
        : "+f"(c[0]), "+f"(c[1]), "+f"(c[2]), "+f"(c[3])
        : "r"(a[0]), "r"(a[1]), "r"(a[2]), "r"(a[3]), "r"(b0), "r"(b1));
}
__device__ __forceinline__ void cpasync16(uint32_t dst, const void* src) {
    asm volatile("cp.async.cg.shared.global [%0], [%1], 16;"
                 :: "r"(dst), "l"(src));
}
#define CP_COMMIT() asm volatile("cp.async.commit_group;" ::: "memory")
#define CP_WAIT(n)  asm volatile("cp.async.wait_group %0;" :: "n"(n) : "memory")

__device__ __forceinline__ __half2 splith2(float a, float b, __half2& lo) {
    __half h0 = __float2half_rn(a), h1 = __float2half_rn(b);
    lo = __halves2half2(__float2half_rn(a - __half2float(h0)),
                        __float2half_rn(b - __half2float(h1)));
    return __halves2half2(h0, h1);
}
__device__ __forceinline__ __half2 h2_rn(float a, float b) {
    return __halves2half2(__float2half_rn(a), __float2half_rn(b));
}

// ---------------------------------------------------------------------------
// mma.sync fp16 GEMM: C = alpha * A @ B^T (fp32 accum).
//   A [M][ldk] fp16, B [N][ldk] fp16 (K-major rows).
//   128x128 CTA tile, BK=64, 128 threads (2x2 warps, 64x64 warp tiles),
//   3-stage cp.async pipeline (1 barrier/chunk), padded smem (SROW=72).
//   Split-K via blockIdx.z = b*kchunks + ks (f32 C offset by zi*sC).
//   ZDIV: row-divide by zb. OUTSPLIT: hi/lo fp16 out. OUTH: fp16 hi out.
//   STATS: per-column sum/sumsq atomics. ROWSTATS: per-row sum/sumsq atomics.
// ---------------------------------------------------------------------------
#define SROW 72
#define BUFB (128u * SROW * 2u)        // 18432 B per operand tile
#define GSMEM (3 * 2 * BUFB + 512)     // 3 stages x (A,B) + zsm = 111104 B

template <bool ZDIV, bool OUTSPLIT, bool OUTH, bool STATS, bool ROWSTATS>
__global__ void __launch_bounds__(128)
gemm_mma(const __half* __restrict__ A_, const __half* __restrict__ B_,
         float* __restrict__ C_, __half* __restrict__ Chi_,
         __half* __restrict__ Clo_,
         int N, int K, int ldk, int kchunks,
         long long sA, long long sB, long long sC,
         float alpha, const float* __restrict__ zb)
{
    extern __shared__ char smem[];
    const int zi = blockIdx.z;
    const int b  = zi / kchunks;
    const int ks = zi - b * kchunks;
    const long long koff = (long long)ks * K;

    const __half* A = A_ + (long long)b * sA + koff;
    const __half* B = B_ + (long long)b * sB + koff;
    const int m0 = blockIdx.y << 7, n0 = blockIdx.x << 7;
    const int tid = threadIdx.x, wid = tid >> 5, lane = tid & 31;
    const int wm = wid & 1, wn = wid >> 1;
    const int tig = lane & 3, grp = lane >> 2;

    const uint32_t sb = smem_u32(smem);
    float* zsm = (float*)(smem + 6 * BUFB);
    if (ZDIV) zsm[tid] = 1.f / zb[(long long)b * 4096 + m0 + tid];

    const int CH = K >> 6;

    float acc[4][8][4];
#pragma unroll
    for (int i = 0; i < 4; i++)
#pragma unroll
        for (int j = 0; j < 8; j++)
#pragma unroll
            for (int t = 0; t < 4; t++) acc[i][j][t] = 0.f;

    // load A,B tiles (128 rows x 64 fp16 each) for K-chunk c into stage st
    auto load = [&](int c, int st) {
        long long kp = (long long)c << 6;
        uint32_t base = sb + (uint32_t)st * (2u * BUFB);
#pragma unroll
        for (int i = 0; i < 8; i++) {
            int slot = tid + (i << 7);
            int row = slot >> 3, u = slot & 7;
            uint32_t d = (uint32_t)(row * (SROW * 2) + (u << 4));
            cpasync16(base + d, A + (long long)(m0 + row) * ldk + kp + (u << 3));
            cpasync16(base + BUFB + d,
                      B + (long long)(n0 + row) * ldk + kp + (u << 3));
        }
        CP_COMMIT();
    };

    load(0, 0);
    if (CH > 1) load(1, 1);

    const uint32_t lrow16 = lane & 15;
    const uint32_t lcol8 = (lane >> 4) << 3;

    int buf = 0;
    for (int c = 0; c < CH; c++) {
        if (c + 1 < CH) { CP_WAIT(1); } else { CP_WAIT(0); }
        __syncthreads();
        if (c + 2 < CH) {
            int nb = buf + 2; if (nb >= 3) nb -= 3;
            load(c + 2, nb);
        }

        uint32_t base = sb + (uint32_t)buf * (2u * BUFB);
#pragma unroll
        for (int ko2 = 0; ko2 < 4; ko2++) {
            const uint32_t ko = ko2 << 4;
            uint32_t a[4][4], bb[4][4];
#pragma unroll
            for (int mi = 0; mi < 4; mi++) {
                uint32_t ad = base +
                    (((wm << 6) + (mi << 4) + lrow16) * SROW + ko + lcol8) * 2;
                ldsm_x4(a[mi][0], a[mi][1], a[mi][2], a[mi][3], ad);
            }
#pragma unroll
            for (int nb = 0; nb < 4; nb++) {
                uint32_t bd = base + BUFB +
                    (((wn << 6) + (nb << 4) + lrow16) * SROW + ko + lcol8) * 2;
                ldsm_x4(bb[nb][0], bb[nb][1], bb[nb][2], bb[nb][3], bd);
            }
#pragma unroll
            for (int mi = 0; mi < 4; mi++)
#pragma unroll
                for (int ni = 0; ni < 8; ni++) {
                    int nb = ni >> 1, hf = ni & 1;
                    mma16816(acc[mi][ni], a[mi], bb[nb][hf], bb[nb][hf + 2]);
                }
        }
        buf++; if (buf == 3) buf = 0;
    }

    // epilogue
    float* C = C_ + (long long)zi * sC;
    __half* Chi = Chi_ + (long long)b * sC;
    __half* Clo = Clo_ + (long long)b * sC;
    float cs1[8][2], cs2[8][2];
    float rs1[4][2], rs2[4][2];
    if (STATS) {
#pragma unroll
        for (int ni = 0; ni < 8; ni++) {
            cs1[ni][0] = cs1[ni][1] = 0.f;
            cs2[ni][0] = cs2[ni][1] = 0.f;
        }
    }
    if (ROWSTATS) {
#pragma unroll
        for (int mi = 0; mi < 4; mi++) {
            rs1[mi][0] = rs1[mi][1] = 0.f;
            rs2[mi][0] = rs2[mi][1] = 0.f;
        }
    }
#pragma unroll
    for (int mi = 0; mi < 4; mi++) {
        int rl = (wm << 6) + (mi << 4) + grp;
        int row = m0 + rl;
        float zr0 = 1.f, zr1 = 1.f;
        if (ZDIV) { zr0 = zsm[rl]; zr1 = zsm[rl + 8]; }
#pragma unroll
        for (int ni = 0; ni < 8; ni++) {
            int col = n0 + (wn << 6) + (ni << 3) + (tig << 1);
            float v0 = acc[mi][ni][0] * alpha;
            float v1 = acc[mi][ni][1] * alpha;
            float v2 = acc[mi][ni][2] * alpha;
            float v3 = acc[mi][ni][3] * alpha;
            if (ZDIV) { v0 *= zr0; v1 *= zr0; v2 *= zr1; v3 *= zr1; }
            if (STATS) {
                cs1[ni][0] += v0 + v2;
                cs1[ni][1] += v1 + v3;
                cs2[ni][0] += v0 * v0 + v2 * v2;
                cs2[ni][1] += v1 * v1 + v3 * v3;
            }
            if (ROWSTATS) {
                rs1[mi][0] += v0 + v1;
                rs2[mi][0] += v0 * v0 + v1 * v1;
                rs1[mi][1] += v2 + v3;
                rs2[mi][1] += v2 * v2 + v3 * v3;
            }
            if (OUTSPLIT) {
                __half2 l0, l1;
                __half2 h0 = splith2(v0, v1, l0);
                __half2 h1 = splith2(v2, v3, l1);
                *(__half2*)(Chi + (long long)row * N + col) = h0;
                *(__half2*)(Chi + (long long)(row + 8) * N + col) = h1;
                *(__half2*)(Clo + (long long)row * N + col) = l0;
                *(__half2*)(Clo + (long long)(row + 8) * N + col) = l1;
            } else if (OUTH) {
                *(__half2*)(Chi + (long long)row * N + col) = h2_rn(v0, v1);
                *(__half2*)(Chi + (long long)(row + 8) * N + col) = h2_rn(v2, v3);
            } else {
                float2 p0; p0.x = v0; p0.y = v1;
                float2 p1; p1.x = v2; p1.y = v3;
                *(float2*)(C + (long long)row * N + col) = p0;
                *(float2*)(C + (long long)(row + 8) * N + col) = p1;
            }
        }
    }
    if (STATS) {
#pragma unroll
        for (int ni = 0; ni < 8; ni++)
#pragma unroll
            for (int h = 0; h < 2; h++) {
                float s1 = cs1[ni][h], s2 = cs2[ni][h];
                s1 += __shfl_down_sync(0xffffffffu, s1, 16);
                s2 += __shfl_down_sync(0xffffffffu, s2, 16);
                s1 += __shfl_down_sync(0xffffffffu, s1, 8);
                s2 += __shfl_down_sync(0xffffffffu, s2, 8);
                s1 += __shfl_down_sync(0xffffffffu, s1, 4);
                s2 += __shfl_down_sync(0xffffffffu, s2, 4);
                if (lane < 4) {
                    int col = n0 + (wn << 6) + (ni << 3) + (lane << 1) + h;
                    atomicAdd(&g_s1[col], s1);
                    atomicAdd(&g_s2[col], s2);
                }
            }
    }
    if (ROWSTATS) {
#pragma unroll
        for (int mi = 0; mi < 4; mi++)
#pragma unroll
            for (int h = 0; h < 2; h++) {
                float s1 = rs1[mi][h], s2 = rs2[mi][h];
                s1 += __shfl_down_sync(0xffffffffu, s1, 2, 4);
                s2 += __shfl_down_sync(0xffffffffu, s2, 2, 4);
                s1 += __shfl_down_sync(0xffffffffu, s1, 1, 4);
                s2 += __shfl_down_sync(0xffffffffu, s2, 1, 4);
                if (tig == 0) {
                    int row = m0 + (wm << 6) + (mi << 4) + grp + (h << 3);
                    atomicAdd(&g_t1[row], s1);
                    atomicAdd(&g_t2[row], s2);
                }
            }
    }
}

// ---------------------------------------------------------------------------
// vk split-K reduce -> fp16 (hi only) with alpha
// ---------------------------------------------------------------------------
__global__ void vkred_kernel()
{
    long long i4 = (long long)(blockIdx.x * 256 + threadIdx.x) * 4;
    int b = (int)(i4 >> 18);
    long long off = i4 & 262143;
    const float* p = g_vkp + ((long long)b * 4) * 262144 + off;
    float4 s0 = *(const float4*)p;
    float4 s1 = *(const float4*)(p + 262144);
    float4 s2 = *(const float4*)(p + 2 * 262144);
    float4 s3 = *(const float4*)(p + 3 * 262144);
    const float al = 1.f / 4096.f;
    float v0 = ((s0.x + s1.x) + (s2.x + s3.x)) * al;
    float v1 = ((s0.y + s1.y) + (s2.y + s3.y)) * al;
    float v2 = ((s0.z + s1.z) + (s2.z + s3.z)) * al;
    float v3 = ((s0.w + s1.w) + (s2.w + s3.w)) * al;
    *(__half2*)(g_vkhi + i4)     = h2_rn(v0, v1);
    *(__half2*)(g_vkhi + i4 + 2) = h2_rn(v2, v3);
}

// ---------------------------------------------------------------------------
__global__ void zero_kernel()
{
    int i = blockIdx.x * 256 + threadIdx.x;
    if (i < 2048) { g_s1[i] = 0.f; g_s2[i] = 0.f; }
    if (i < 512)  { g_t1[i] = 0.f; g_t2[i] = 0.f; }
    if (i < 4096) g_ksum[i] = 0.f;
}

__global__ void bn1_finalize(const float* __restrict__ gamma,
                             const float* __restrict__ beta)
{
    int c = blockIdx.x * 256 + threadIdx.x;
    const float inv = 1.f / (BATCH * NPIX);
    float mean = g_s1[c] * inv;
    float var = g_s2[c] * inv - mean * mean;
    float av = gamma[c] * rsqrtf(var + 1e-5f);
    g_a1[c] = av;
    g_b1[c] = beta[c] - mean * av;
}

__global__ void bn2_finalize(const float* __restrict__ gamma,
                             const float* __restrict__ beta)
{
    int c = blockIdx.x * 256 + threadIdx.x;
    const float inv = 1.f / (BATCH * NPIX);
    float mean = g_t1[c] * inv;
    float var = g_t2[c] * inv - mean * mean;
    float av = gamma[c] * rsqrtf(var + 1e-5f);
    g_a2[c] = av;
    g_b2[c] = beta[c] - mean * av;
}

// q: sigmoid(affine(y[:, 0:512])) -> q^T fp16
__global__ void q_kernel()
{
    int i = blockIdx.x * 256 + threadIdx.x;
    int r = i >> 7;
    int dg = (i & 127) << 2;
    long long yb = (long long)r * C4 + dg;
    __half2 yh0 = *(const __half2*)(g_ythi + yb);
    __half2 yh1 = *(const __half2*)(g_ythi + yb + 2);
    __half2 yl0 = *(const __half2*)(g_ytlo + yb);
    __half2 yl1 = *(const __half2*)(g_ytlo + yb + 2);
    float4 a4 = *(const float4*)(g_a1 + dg);
    float4 b4 = *(const float4*)(g_b1 + dg);
    float y0 = __half2float(yh0.x) + __half2float(yl0.x);
    float y1 = __half2float(yh0.y) + __half2float(yl0.y);
    float y2 = __half2float(yh1.x) + __half2float(yl1.x);
    float y3 = __half2float(yh1.y) + __half2float(yl1.y);
    float q0 = 1.f / (1.f + expf(-(a4.x * y0 + b4.x)));
    float q1 = 1.f / (1.f + expf(-(a4.y * y1 + b4.y)));
    float q2 = 1.f / (1.f + expf(-(a4.z * y2 + b4.z)));
    float q3 = 1.f / (1.f + expf(-(a4.w * y3 + b4.w)));
    long long o = (long long)r * DIM + dg;
    *(__half2*)(g_qthi + o)     = h2_rn(q0, q1);
    *(__half2*)(g_qthi + o + 2) = h2_rn(q2, q3);
}

// k,v: 64x64 transpose y^T -> [b][d][n]; k hi fp16, v hi fp16, ksum
__global__ void kvt_kernel()
{
    __shared__ float tk[64][65], tv[64][65];
    int bz = blockIdx.z;
    int n0 = blockIdx.x << 6, d0 = blockIdx.y << 6;
    int tx = threadIdx.x, ty = threadIdx.y;
    int dloc = tx << 1;
    float2 akp = *(const float2*)(g_a1 + 512 + d0 + dloc);
    float2 bkp = *(const float2*)(g_b1 + 512 + d0 + dloc);
    float2 avp = *(const float2*)(g_a1 + 1024 + d0 + dloc);
    float2 bvp = *(const float2*)(g_b1 + 1024 + d0 + dloc);
#pragma unroll
    for (int i = 0; i < 8; i++) {
        int nl = ty + (i << 3);
        long long rb = ((long long)(bz << 12) + n0 + nl) * C4;
        __half2 kh2 = *(const __half2*)(g_ythi + rb + 512 + d0 + dloc);
        __half2 kl2 = *(const __half2*)(g_ytlo + rb + 512 + d0 + dloc);
        __half2 vh2 = *(const __half2*)(g_ythi + rb + 1024 + d0 + dloc);
        __half2 vl2 = *(const __half2*)(g_ytlo + rb + 1024 + d0 + dloc);
        float k0 = __half2float(kh2.x) + __half2float(kl2.x);
        float k1 = __half2float(kh2.y) + __half2float(kl2.y);
        float v0 = __half2float(vh2.x) + __half2float(vl2.x);
        float v1 = __half2float(vh2.y) + __half2float(vl2.y);
        tk[nl][dloc]     = 1.f / (1.f + expf(-(akp.x * k0 + bkp.x)));
        tk[nl][dloc + 1] = 1.f / (1.f + expf(-(akp.y * k1 + bkp.y)));
        tv[nl][dloc]     = avp.x * v0 + bvp.x;
        tv[nl][dloc + 1] = avp.y * v1 + bvp.y;
    }
    __syncthreads();
#pragma unroll
    for (int i = 0; i < 8; i++) {
        int dl = ty + (i << 3);
        int d = d0 + dl;
        int nl = tx << 1;
        float k0 = tk[nl][dl], k1 = tk[nl + 1][dl];
        float v0 = tv[nl][dl], v1 = tv[nl + 1][dl];
        long long o = ((long long)(bz << 9) + d) * NPIX + n0 + nl;
        *(__half2*)(g_khi + o) = h2_rn(k0, k1);
        *(__half2*)(g_vhi + o) = h2_rn(v0, v1);
        float s = k0 + k1;
#pragma unroll
        for (int off = 16; off > 0; off >>= 1)
            s += __shfl_down_sync(0xffffffffu, s, off);
        if (tx == 0) atomicAdd(&g_ksum[(bz << 9) + d], s);
    }
}

// z[r] = sum_d kmean[d] * q[r][d] + eps
__global__ void z_kernel()
{
    __shared__ float km[512];
    int r0 = blockIdx.x << 3;
    int bb = r0 >> 12;
    for (int i = threadIdx.x; i < 512; i += 256)
        km[i] = g_ksum[(bb << 9) + i] * (1.f / NPIX);
    __syncthreads();
    int w = threadIdx.x >> 5, lane = threadIdx.x & 31;
    int r = r0 + w;
    const __half* qh = g_qthi + (long long)r * DIM;
    float s = 0.f;
#pragma unroll
    for (int i = 0; i < 16; i++) {
        int d = lane + (i << 5);
        s += km[d] * __half2float(qh[d]);
    }
#pragma unroll
    for (int off = 16; off > 0; off >>= 1)
        s += __shfl_down_sync(0xffffffffu, s, off);
    if (lane == 0) g_z[r] = s + 5e-4f;
}

// RMSNorm row + anw + SiLU(gate) -> o^T fp16 (hi only)
__global__ void rmsgate_kernel(const float* __restrict__ anw)
{
    __shared__ float red[4];
    int r = blockIdx.x;
    int t = threadIdx.x;
    int dg = t << 2;
    long long arow = (long long)r * DIM + dg;
    __half2 ah0 = *(const __half2*)(g_athi + arow);
    __half2 ah1 = *(const __half2*)(g_athi + arow + 2);
    __half2 al0 = *(const __half2*)(g_atlo + arow);
    __half2 al1 = *(const __half2*)(g_atlo + arow + 2);
    float a0 = __half2float(ah0.x) + __half2float(al0.x);
    float a1 = __half2float(ah0.y) + __half2float(al0.y);
    float a2 = __half2float(ah1.x) + __half2float(al1.x);
    float a3 = __half2float(ah1.y) + __half2float(al1.y);
    float ss = a0 * a0 + a1 * a1 + a2 * a2 + a3 * a3;
    int lane = t & 31, w = t >> 5;
#pragma unroll
    for (int off = 16; off > 0; off >>= 1)
        ss += __shfl_down_sync(0xffffffffu, ss, off);
    if (lane == 0) red[w] = ss;
    __syncthreads();
    float tot = red[0] + red[1] + red[2] + red[3];
    float rms = rsqrtf(tot * (1.f / DIM) + 1e-6f);

    long long grow = (long long)r * C4 + 1536 + dg;
    __half2 gh0 = *(const __half2*)(g_ythi + grow);
    __half2 gh1 = *(const __half2*)(g_ythi + grow + 2);
    __half2 gl0 = *(const __half2*)(g_ytlo + grow);
    __half2 gl1 = *(const __half2*)(g_ytlo + grow + 2);
    float yg0 = __half2float(gh0.x) + __half2float(gl0.x);
    float yg1 = __half2float(gh0.y) + __half2float(gl0.y);
    float yg2 = __half2float(gh1.x) + __half2float(gl1.x);
    float yg3 = __half2float(gh1.y) + __half2float(gl1.y);
    float4 ga = *(const float4*)(g_a1 + 1536 + dg);
    float4 gb = *(const float4*)(g_b1 + 1536 + dg);
    float4 wn = *(const float4*)(anw + dg);
    float g0 = ga.x * yg0 + gb.x, g1 = ga.y * yg1 + gb.y;
    float g2 = ga.z * yg2 + gb.z, g3 = ga.w * yg3 + gb.w;
    float o0 = a0 * rms * wn.x * (g0 / (1.f + expf(-g0)));
    float o1 = a1 * rms * wn.y * (g1 / (1.f + expf(-g1)));
    float o2 = a2 * rms * wn.z * (g2 / (1.f + expf(-g2)));
    float o3 = a3 * rms * wn.w * (g3 / (1.f + expf(-g3)));
    long long o = (long long)r * DIM + dg;
    *(__half2*)(g_othi + o)     = h2_rn(o0, o1);
    *(__half2*)(g_othi + o + 2) = h2_rn(o2, o3);
}

// BN2 apply: out = a2*ypre(fp16) + b2, f32 out
__global__ void bnapply_kernel(float* __restrict__ out)
{
    long long i = (long long)(blockIdx.x * blockDim.x + threadIdx.x) * 4;
    int c = (int)((i >> 12) & 511);
    float a = g_a2[c], bb = g_b2[c];
    __half2 p0 = *(const __half2*)(g_ypreh + i);
    __half2 p1 = *(const __half2*)(g_ypreh + i + 2);
    float4 v;
    v.x = a * __half2float(p0.x) + bb;
    v.y = a * __half2float(p0.y) + bb;
    v.z = a * __half2float(p1.x) + bb;
    v.w = a * __half2float(p1.y) + bb;
    *reinterpret_cast<float4*>(out + i) = v;
}

// f32 -> fp16 (hi only)
__global__ void convert_half(const float* __restrict__ s,
                             __half* __restrict__ hi, int n)
{
    int i = blockIdx.x * blockDim.x + threadIdx.x;
    if (i < n) hi[i] = __float2half_rn(s[i]);
}

// transpose f32 src [b][R][Cc] -> fp16 hi-only dst [b][Cc][R]
__global__ void transpose_half(const float* __restrict__ src,
                               __half* __restrict__ dhi, int R, int Cc)
{
    __shared__ float t[32][33];
    int b = blockIdx.z;
    long long o = (long long)b * R * Cc;
    src += o; dhi += o;
    int c0 = blockIdx.x * 32, r0 = blockIdx.y * 32;
    int tx = threadIdx.x, ty = threadIdx.y;
#pragma unroll
    for (int i = 0; i < 4; i++)
        t[ty + 8 * i][tx] = src[(long long)(r0 + ty + 8 * i) * Cc + c0 + tx];
    __syncthreads();
#pragma unroll
    for (int i = 0; i < 4; i++) {
        int cc = c0 + ty + 8 * i;
        dhi[(long long)cc * R + r0 + tx] = __float2half_rn(t[tx][ty + 8 * i]);
    }
}

// ---------------------------------------------------------------------------
extern "C" void kernel_launch(void* const* d_in, const int* in_sizes, int n_in,
                              void* d_out, int out_size)
{
    const float* x           = (const float*)d_in[0];
    const float* qkvg_w      = (const float*)d_in[1];
    const float* qkvg_gamma  = (const float*)d_in[2];
    const float* qkvg_beta   = (const float*)d_in[3];
    const float* attn_norm_w = (const float*)d_in[4];
    const float* proj_w      = (const float*)d_in[5];
    const float* proj_gamma  = (const float*)d_in[6];
    const float* proj_beta   = (const float*)d_in[7];
    float* out = (float*)d_out;

    cudaFuncSetAttribute(gemm_mma<false, true, false, true, false>,
                         cudaFuncAttributeMaxDynamicSharedMemorySize, GSMEM);
    cudaFuncSetAttribute(gemm_mma<false, false, false, false, false>,
                         cudaFuncAttributeMaxDynamicSharedMemorySize, GSMEM);
    cudaFuncSetAttribute(gemm_mma<true, true, false, false, false>,
                         cudaFuncAttributeMaxDynamicSharedMemorySize, GSMEM);
    cudaFuncSetAttribute(gemm_mma<false, false, true, false, true>,
                         cudaFuncAttributeMaxDynamicSharedMemorySize, GSMEM);

    float *pvkp, *pz;
    __half *pythi, *pytlo, *pathi, *patlo, *pypreh;
    __half *pkhi, *pvhi, *pqthi, *pxthi, *pothi, *pvkhi, *pwqhi, *ppwhi;
    cudaGetSymbolAddress((void**)&pythi, g_ythi);
    cudaGetSymbolAddress((void**)&pytlo, g_ytlo);
    cudaGetSymbolAddress((void**)&pathi, g_athi);
    cudaGetSymbolAddress((void**)&patlo, g_atlo);
    cudaGetSymbolAddress((void**)&pypreh, g_ypreh);
    cudaGetSymbolAddress((void**)&pvkp,  g_vkp);
    cudaGetSymbolAddress((void**)&pz,    g_z);
    cudaGetSymbolAddress((void**)&pkhi,  g_khi);
    cudaGetSymbolAddress((void**)&pvhi,  g_vhi);
    cudaGetSymbolAddress((void**)&pqthi, g_qthi);
    cudaGetSymbolAddress((void**)&pxthi, g_xthi);
    cudaGetSymbolAddress((void**)&pothi, g_othi);
    cudaGetSymbolAddress((void**)&pvkhi, g_vkhi);
    cudaGetSymbolAddress((void**)&pwqhi, g_wqhi);
    cudaGetSymbolAddress((void**)&ppwhi, g_pwhi);

    const long long sQKV = (long long)DIM * NPIX;   // 2097152
    const long long sYT  = (long long)NPIX * C4;    // 8388608
    const long long sVK  = (long long)DIM * DIM;    // 262144

    zero_kernel<<<32, 256>>>();
    convert_half<<<4096, 256>>>(qkvg_w, pwqhi, C4 * DIM);
    convert_half<<<1024, 256>>>(proj_w, ppwhi, DIM * DIM);
    transpose_half<<<dim3(128, 16, BATCH), dim3(32, 8)>>>(x, pxthi, DIM, NPIX);

    // 1) y^T = x^T @ w^T -> fp16 hi/lo + fused BN1 column stats
    gemm_mma<false, true, false, true, false><<<dim3(16, 32, BATCH), 128, GSMEM>>>(
        pxthi, pwqhi, nullptr, pythi, pytlo,
        2048, 512, 512, 1, sQKV, 0, sYT, 1.f, nullptr);

    // 2) BN1 finalize
    bn1_finalize<<<8, 256>>>(qkvg_gamma, qkvg_beta);

    // 3) q^T fp16; k hi + v hi -> [d][n] + ksum
    q_kernel<<<16384, 256>>>();
    kvt_kernel<<<dim3(64, 8, BATCH), dim3(32, 8)>>>();

    // 4) z
    z_kernel<<<4096, 256>>>();

    // 5) vk = v @ k^T, split-K x4; reduce -> fp16 hi
    gemm_mma<false, false, false, false, false><<<dim3(4, 4, BATCH * 4), 128, GSMEM>>>(
        pvhi, pkhi, pvkp, nullptr, nullptr,
        512, 1024, 4096, 4, sQKV, sQKV, sVK, 1.f, nullptr);
    vkred_kernel<<<2048, 256>>>();

    // 6) attn^T = q^T @ vk^T / z -> hi/lo fp16
    gemm_mma<true, true, false, false, false><<<dim3(4, 32, BATCH), 128, GSMEM>>>(
        pqthi, pvkhi, nullptr, pathi, patlo,
        512, 512, 512, 1, sQKV, sVK, sQKV, 1.f, pz);

    // 7) RMSNorm + gate -> o^T fp16
    rmsgate_kernel<<<32768, 128>>>(attn_norm_w);

    // 8) ypre = proj_w @ o (fp16 out) + fused BN2 row stats
    gemm_mma<false, false, true, false, true><<<dim3(32, 4, BATCH), 128, GSMEM>>>(
        ppwhi, pothi, nullptr, pypreh, nullptr,
        4096, 512, 512, 1, 0, sQKV, sQKV, 1.f, nullptr);

    // 9) BN2 finalize + apply
    bn2_finalize<<<2, 256>>>(proj_gamma, proj_beta);
    bnapply_kernel<<<16384, 256>>>(out);
}

// round 16
// speedup vs baseline: 1.0990x; 1.0990x over previous
#include <cuda_runtime.h>
#include <cuda_fp16.h>
#include <math.h>
#include <stdint.h>

// ---------------------------------------------------------------------------
// SHMA block: pure fp16 mma.sync GEMMs (fp32 accum), BK=64, 2-stage
// cp.async pipeline, n-major dataflow, BN1/BN2 stats fused into GEMM
// epilogues. y stored fp16 hi-only; attn kept hi/lo; ypre fp16.
// B=8, dim=d=512, N=4096, qkvg=2048.
// ---------------------------------------------------------------------------

#define BATCH 8
#define DIM   512
#define NPIX  4096
#define C4    2048

// ---------------- scratch (static device globals) --------------------------
__device__ __half g_ythi[67108864];                   // y^T (8*4096,2048)
__device__ __half g_athi[16777216], g_atlo[16777216]; // attn^T (8*4096,512)
__device__ __half g_ypreh[16777216];                  // ypre (8, 512, 4096) fp16
__device__ float g_vkp[8388608];                      // vk split-K partials
__device__ __half g_khi[16777216];                    // k [b][d][n]
__device__ __half g_vhi[16777216];                    // v [b][d][n]
__device__ __half g_qthi[16777216];                   // q^T [b][n][d]
__device__ __half g_xthi[16777216];                   // x^T [b][n][c]
__device__ __half g_othi[16777216];                   // o^T [b][n][d]
__device__ __half g_vkhi[2097152];                    // vk [b][d][e]
__device__ __half g_wqhi[1048576];                    // qkvg_w
__device__ __half g_pwhi[262144];                     // proj_w
__device__ float g_a1[2048], g_b1[2048], g_a2[512], g_b2[512];
__device__ float g_s1[2048], g_s2[2048];              // BN1 accum
__device__ float g_t1[512], g_t2[512];                // BN2 accum
__device__ float g_ksum[4096], g_z[32768];

// ---------------- helpers ---------------------------------------------------
__device__ __forceinline__ uint32_t smem_u32(const void* p) {
    uint32_t a;
    asm("{ .reg .u64 t; cvta.to.shared.u64 t, %1; cvt.u32.u64 %0, t; }"
        : "=r"(a) : "l"(p));
    return a;
}
__device__ __forceinline__ void ldsm_x4(uint32_t& r0, uint32_t& r1,
                                        uint32_t& r2, uint32_t& r3,
                                        uint32_t addr) {
    asm volatile("ldmatrix.sync.aligned.m8n8.x4.shared.b16 {%0,%1,%2,%3}, [%4];"
                 : "=r"(r0), "=r"(r1), "=r"(r2), "=r"(r3) : "r"(addr));
}
__device__ __forceinline__ void mma16816(float* c, const uint32_t* a,
                                         uint32_t b0, uint32_t b1) {
    asm volatile(
        "mma.sync.aligned.m16n8k16.row.col.f32.f16.f16.f32 "
        "{%0,%1,%2,%3}, {%4,%5,%6,%7}, {%8,%9}, {%0,%1,%2,%3};"
        : "+f"(c[0]), "+f"(c[1]), "+f"(c[2]), "+f"(c[3])
        : "r"(a[0]), "r"(a[1]), "r"(a[2]), "r"(a[3]), "r"(b0), "r"(b1));
}
__device__ __forceinline__ void cpasync16(uint32_t dst, const void* src) {
    asm volatile("cp.async.cg.shared.global [%0], [%1], 16;"
                 :: "r"(dst), "l"(src));
}
#define CP_COMMIT() asm volatile("cp.async.commit_group;" ::: "memory")
#define CP_WAIT(n)  asm volatile("cp.async.wait_group %0;" :: "n"(n) : "memory")

__device__ __forceinline__ __half2 splith2(float a, float b, __half2& lo) {
    __half h0 = __float2half_rn(a), h1 = __float2half_rn(b);
    lo = __halves2half2(__float2half_rn(a - __half2float(h0)),
                        __float2half_rn(b - __half2float(h1)));
    return __halves2half2(h0, h1);
}
__device__ __forceinline__ __half2 h2_rn(float a, float b) {
    return __halves2half2(__float2half_rn(a), __float2half_rn(b));
}

// ---------------------------------------------------------------------------
// mma.sync fp16 GEMM: C = alpha * A @ B^T (fp32 accum).
//   A [M][ldk] fp16, B [N][ldk] fp16 (K-major rows).
//   128x128 CTA tile, BK=64, 128 threads (2x2 warps, 64x64 warp tiles),
//   2-stage cp.async double buffer, padded smem (SROW=72: 144B rows).
//   Split-K via blockIdx.z = b*kchunks + ks (f32 C offset by zi*sC).
//   ZDIV: row-divide by zb. OUTSPLIT: hi/lo fp16 out. OUTH: fp16 hi out.
//   STATS: per-column sum/sumsq atomics. ROWSTATS: per-row sum/sumsq atomics.
// ---------------------------------------------------------------------------
#define SROW 72
#define BUFB (128u * SROW * 2u)        // 18432 B per operand tile
#define GSMEM (2 * 2 * BUFB + 512)     // 2 stages x (A,B) + zsm = 74240 B

template <bool ZDIV, bool OUTSPLIT, bool OUTH, bool STATS, bool ROWSTATS>
__global__ void __launch_bounds__(128)
gemm_mma(const __half* __restrict__ A_, const __half* __restrict__ B_,
         float* __restrict__ C_, __half* __restrict__ Chi_,
         __half* __restrict__ Clo_,
         int N, int K, int ldk, int kchunks,
         long long sA, long long sB, long long sC,
         float alpha, const float* __restrict__ zb)
{
    extern __shared__ char smem[];
    const int zi = blockIdx.z;
    const int b  = zi / kchunks;
    const int ks = zi - b * kchunks;
    const long long koff = (long long)ks * K;

    const __half* A = A_ + (long long)b * sA + koff;
    const __half* B = B_ + (long long)b * sB + koff;
    const int m0 = blockIdx.y << 7, n0 = blockIdx.x << 7;
    const int tid = threadIdx.x, wid = tid >> 5, lane = tid & 31;
    const int wm = wid & 1, wn = wid >> 1;
    const int tig = lane & 3, grp = lane >> 2;

    const uint32_t sb = smem_u32(smem);
    float* zsm = (float*)(smem + 4 * BUFB);
    if (ZDIV) zsm[tid] = 1.f / zb[(long long)b * 4096 + m0 + tid];

    const int CH = K >> 6;

    float acc[4][8][4];
#pragma unroll
    for (int i = 0; i < 4; i++)
#pragma unroll
        for (int j = 0; j < 8; j++)
#pragma unroll
            for (int t = 0; t < 4; t++) acc[i][j][t] = 0.f;

    auto load = [&](int c, int st) {
        long long kp = (long long)c << 6;
        uint32_t base = sb + (uint32_t)st * (2u * BUFB);
#pragma unroll
        for (int i = 0; i < 8; i++) {
            int slot = tid + (i << 7);
            int row = slot >> 3, u = slot & 7;
            uint32_t d = (uint32_t)(row * (SROW * 2) + (u << 4));
            cpasync16(base + d, A + (long long)(m0 + row) * ldk + kp + (u << 3));
            cpasync16(base + BUFB + d,
                      B + (long long)(n0 + row) * ldk + kp + (u << 3));
        }
        CP_COMMIT();
    };

    load(0, 0);

    const uint32_t lrow16 = lane & 15;
    const uint32_t lcol8 = (lane >> 4) << 3;

    int buf = 0;
    for (int c = 0; c < CH; c++) {
        if (c + 1 < CH) { load(c + 1, buf ^ 1); CP_WAIT(1); }
        else            { CP_WAIT(0); }
        __syncthreads();

        uint32_t base = sb + (uint32_t)buf * (2u * BUFB);
#pragma unroll
        for (int ko2 = 0; ko2 < 4; ko2++) {
            const uint32_t ko = ko2 << 4;
            uint32_t a[4][4], bb[4][4];
#pragma unroll
            for (int mi = 0; mi < 4; mi++) {
                uint32_t ad = base +
                    (((wm << 6) + (mi << 4) + lrow16) * SROW + ko + lcol8) * 2;
                ldsm_x4(a[mi][0], a[mi][1], a[mi][2], a[mi][3], ad);
            }
#pragma unroll
            for (int nb = 0; nb < 4; nb++) {
                uint32_t bd = base + BUFB +
                    (((wn << 6) + (nb << 4) + lrow16) * SROW + ko + lcol8) * 2;
                ldsm_x4(bb[nb][0], bb[nb][1], bb[nb][2], bb[nb][3], bd);
            }
#pragma unroll
            for (int mi = 0; mi < 4; mi++)
#pragma unroll
                for (int ni = 0; ni < 8; ni++) {
                    int nb = ni >> 1, hf = ni & 1;
                    mma16816(acc[mi][ni], a[mi], bb[nb][hf], bb[nb][hf + 2]);
                }
        }
        __syncthreads();
        buf ^= 1;
    }

    // epilogue
    float* C = C_ + (long long)zi * sC;
    __half* Chi = Chi_ + (long long)b * sC;
    __half* Clo = Clo_ + (long long)b * sC;
    float cs1[8][2], cs2[8][2];
    float rs1[4][2], rs2[4][2];
    if (STATS) {
#pragma unroll
        for (int ni = 0; ni < 8; ni++) {
            cs1[ni][0] = cs1[ni][1] = 0.f;
            cs2[ni][0] = cs2[ni][1] = 0.f;
        }
    }
    if (ROWSTATS) {
#pragma unroll
        for (int mi = 0; mi < 4; mi++) {
            rs1[mi][0] = rs1[mi][1] = 0.f;
            rs2[mi][0] = rs2[mi][1] = 0.f;
        }
    }
#pragma unroll
    for (int mi = 0; mi < 4; mi++) {
        int rl = (wm << 6) + (mi << 4) + grp;
        int row = m0 + rl;
        float zr0 = 1.f, zr1 = 1.f;
        if (ZDIV) { zr0 = zsm[rl]; zr1 = zsm[rl + 8]; }
#pragma unroll
        for (int ni = 0; ni < 8; ni++) {
            int col = n0 + (wn << 6) + (ni << 3) + (tig << 1);
            float v0 = acc[mi][ni][0] * alpha;
            float v1 = acc[mi][ni][1] * alpha;
            float v2 = acc[mi][ni][2] * alpha;
            float v3 = acc[mi][ni][3] * alpha;
            if (ZDIV) { v0 *= zr0; v1 *= zr0; v2 *= zr1; v3 *= zr1; }
            if (STATS) {
                cs1[ni][0] += v0 + v2;
                cs1[ni][1] += v1 + v3;
                cs2[ni][0] += v0 * v0 + v2 * v2;
                cs2[ni][1] += v1 * v1 + v3 * v3;
            }
            if (ROWSTATS) {
                rs1[mi][0] += v0 + v1;
                rs2[mi][0] += v0 * v0 + v1 * v1;
                rs1[mi][1] += v2 + v3;
                rs2[mi][1] += v2 * v2 + v3 * v3;
            }
            if (OUTSPLIT) {
                __half2 l0, l1;
                __half2 h0 = splith2(v0, v1, l0);
                __half2 h1 = splith2(v2, v3, l1);
                *(__half2*)(Chi + (long long)row * N + col) = h0;
                *(__half2*)(Chi + (long long)(row + 8) * N + col) = h1;
                *(__half2*)(Clo + (long long)row * N + col) = l0;
                *(__half2*)(Clo + (long long)(row + 8) * N + col) = l1;
            } else if (OUTH) {
                *(__half2*)(Chi + (long long)row * N + col) = h2_rn(v0, v1);
                *(__half2*)(Chi + (long long)(row + 8) * N + col) = h2_rn(v2, v3);
            } else {
                float2 p0; p0.x = v0; p0.y = v1;
                float2 p1; p1.x = v2; p1.y = v3;
                *(float2*)(C + (long long)row * N + col) = p0;
                *(float2*)(C + (long long)(row + 8) * N + col) = p1;
            }
        }
    }
    if (STATS) {
#pragma unroll
        for (int ni = 0; ni < 8; ni++)
#pragma unroll
            for (int h = 0; h < 2; h++) {
                float s1 = cs1[ni][h], s2 = cs2[ni][h];
                s1 += __shfl_down_sync(0xffffffffu, s1, 16);
                s2 += __shfl_down_sync(0xffffffffu, s2, 16);
                s1 += __shfl_down_sync(0xffffffffu, s1, 8);
                s2 += __shfl_down_sync(0xffffffffu, s2, 8);
                s1 += __shfl_down_sync(0xffffffffu, s1, 4);
                s2 += __shfl_down_sync(0xffffffffu, s2, 4);
                if (lane < 4) {
                    int col = n0 + (wn << 6) + (ni << 3) + (lane << 1) + h;
                    atomicAdd(&g_s1[col], s1);
                    atomicAdd(&g_s2[col], s2);
                }
            }
    }
    if (ROWSTATS) {
#pragma unroll
        for (int mi = 0; mi < 4; mi++)
#pragma unroll
            for (int h = 0; h < 2; h++) {
                float s1 = rs1[mi][h], s2 = rs2[mi][h];
                s1 += __shfl_down_sync(0xffffffffu, s1, 2, 4);
                s2 += __shfl_down_sync(0xffffffffu, s2, 2, 4);
                s1 += __shfl_down_sync(0xffffffffu, s1, 1, 4);
                s2 += __shfl_down_sync(0xffffffffu, s2, 1, 4);
                if (tig == 0) {
                    int row = m0 + (wm << 6) + (mi << 4) + grp + (h << 3);
                    atomicAdd(&g_t1[row], s1);
                    atomicAdd(&g_t2[row], s2);
                }
            }
    }
}

// ---------------------------------------------------------------------------
// vk split-K reduce -> fp16 (hi only) with alpha
// ---------------------------------------------------------------------------
__global__ void vkred_kernel()
{
    long long i4 = (long long)(blockIdx.x * 256 + threadIdx.x) * 4;
    int b = (int)(i4 >> 18);
    long long off = i4 & 262143;
    const float* p = g_vkp + ((long long)b * 4) * 262144 + off;
    float4 s0 = *(const float4*)p;
    float4 s1 = *(const float4*)(p + 262144);
    float4 s2 = *(const float4*)(p + 2 * 262144);
    float4 s3 = *(const float4*)(p + 3 * 262144);
    const float al = 1.f / 4096.f;
    float v0 = ((s0.x + s1.x) + (s2.x + s3.x)) * al;
    float v1 = ((s0.y + s1.y) + (s2.y + s3.y)) * al;
    float v2 = ((s0.z + s1.z) + (s2.z + s3.z)) * al;
    float v3 = ((s0.w + s1.w) + (s2.w + s3.w)) * al;
    *(__half2*)(g_vkhi + i4)     = h2_rn(v0, v1);
    *(__half2*)(g_vkhi + i4 + 2) = h2_rn(v2, v3);
}

// ---------------------------------------------------------------------------
__global__ void zero_kernel()
{
    int i = blockIdx.x * 256 + threadIdx.x;
    if (i < 2048) { g_s1[i] = 0.f; g_s2[i] = 0.f; }
    if (i < 512)  { g_t1[i] = 0.f; g_t2[i] = 0.f; }
    if (i < 4096) g_ksum[i] = 0.f;
}

__global__ void bn1_finalize(const float* __restrict__ gamma,
                             const float* __restrict__ beta)
{
    int c = blockIdx.x * 256 + threadIdx.x;
    const float inv = 1.f / (BATCH * NPIX);
    float mean = g_s1[c] * inv;
    float var = g_s2[c] * inv - mean * mean;
    float av = gamma[c] * rsqrtf(var + 1e-5f);
    g_a1[c] = av;
    g_b1[c] = beta[c] - mean * av;
}

__global__ void bn2_finalize(const float* __restrict__ gamma,
                             const float* __restrict__ beta)
{
    int c = blockIdx.x * 256 + threadIdx.x;
    const float inv = 1.f / (BATCH * NPIX);
    float mean = g_t1[c] * inv;
    float var = g_t2[c] * inv - mean * mean;
    float av = gamma[c] * rsqrtf(var + 1e-5f);
    g_a2[c] = av;
    g_b2[c] = beta[c] - mean * av;
}

// q: sigmoid(affine(y[:, 0:512])) -> q^T fp16
__global__ void q_kernel()
{
    int i = blockIdx.x * 256 + threadIdx.x;
    int r = i >> 7;
    int dg = (i & 127) << 2;
    long long yb = (long long)r * C4 + dg;
    __half2 yh0 = *(const __half2*)(g_ythi + yb);
    __half2 yh1 = *(const __half2*)(g_ythi + yb + 2);
    float4 a4 = *(const float4*)(g_a1 + dg);
    float4 b4 = *(const float4*)(g_b1 + dg);
    float y0 = __half2float(yh0.x);
    float y1 = __half2float(yh0.y);
    float y2 = __half2float(yh1.x);
    float y3 = __half2float(yh1.y);
    float q0 = 1.f / (1.f + expf(-(a4.x * y0 + b4.x)));
    float q1 = 1.f / (1.f + expf(-(a4.y * y1 + b4.y)));
    float q2 = 1.f / (1.f + expf(-(a4.z * y2 + b4.z)));
    float q3 = 1.f / (1.f + expf(-(a4.w * y3 + b4.w)));
    long long o = (long long)r * DIM + dg;
    *(__half2*)(g_qthi + o)     = h2_rn(q0, q1);
    *(__half2*)(g_qthi + o + 2) = h2_rn(q2, q3);
}

// k,v: 64x64 transpose y^T -> [b][d][n]; k hi fp16, v hi fp16, ksum
__global__ void kvt_kernel()
{
    __shared__ float tk[64][65], tv[64][65];
    int bz = blockIdx.z;
    int n0 = blockIdx.x << 6, d0 = blockIdx.y << 6;
    int tx = threadIdx.x, ty = threadIdx.y;
    int dloc = tx << 1;
    float2 akp = *(const float2*)(g_a1 + 512 + d0 + dloc);
    float2 bkp = *(const float2*)(g_b1 + 512 + d0 + dloc);
    float2 avp = *(const float2*)(g_a1 + 1024 + d0 + dloc);
    float2 bvp = *(const float2*)(g_b1 + 1024 + d0 + dloc);
#pragma unroll
    for (int i = 0; i < 8; i++) {
        int nl = ty + (i << 3);
        long long rb = ((long long)(bz << 12) + n0 + nl) * C4;
        __half2 kh2 = *(const __half2*)(g_ythi + rb + 512 + d0 + dloc);
        __half2 vh2 = *(const __half2*)(g_ythi + rb + 1024 + d0 + dloc);
        float k0 = __half2float(kh2.x);
        float k1 = __half2float(kh2.y);
        float v0 = __half2float(vh2.x);
        float v1 = __half2float(vh2.y);
        tk[nl][dloc]     = 1.f / (1.f + expf(-(akp.x * k0 + bkp.x)));
        tk[nl][dloc + 1] = 1.f / (1.f + expf(-(akp.y * k1 + bkp.y)));
        tv[nl][dloc]     = avp.x * v0 + bvp.x;
        tv[nl][dloc + 1] = avp.y * v1 + bvp.y;
    }
    __syncthreads();
#pragma unroll
    for (int i = 0; i < 8; i++) {
        int dl = ty + (i << 3);
        int d = d0 + dl;
        int nl = tx << 1;
        float k0 = tk[nl][dl], k1 = tk[nl + 1][dl];
        float v0 = tv[nl][dl], v1 = tv[nl + 1][dl];
        long long o = ((long long)(bz << 9) + d) * NPIX + n0 + nl;
        *(__half2*)(g_khi + o) = h2_rn(k0, k1);
        *(__half2*)(g_vhi + o) = h2_rn(v0, v1);
        float s = k0 + k1;
#pragma unroll
        for (int off = 16; off > 0; off >>= 1)
            s += __shfl_down_sync(0xffffffffu, s, off);
        if (tx == 0) atomicAdd(&g_ksum[(bz << 9) + d], s);
    }
}

// z[r] = sum_d kmean[d] * q[r][d] + eps
__global__ void z_kernel()
{
    __shared__ float km[512];
    int r0 = blockIdx.x << 3;
    int bb = r0 >> 12;
    for (int i = threadIdx.x; i < 512; i += 256)
        km[i] = g_ksum[(bb << 9) + i] * (1.f / NPIX);
    __syncthreads();
    int w = threadIdx.x >> 5, lane = threadIdx.x & 31;
    int r = r0 + w;
    const __half* qh = g_qthi + (long long)r * DIM;
    float s = 0.f;
#pragma unroll
    for (int i = 0; i < 16; i++) {
        int d = lane + (i << 5);
        s += km[d] * __half2float(qh[d]);
    }
#pragma unroll
    for (int off = 16; off > 0; off >>= 1)
        s += __shfl_down_sync(0xffffffffu, s, off);
    if (lane == 0) g_z[r] = s + 5e-4f;
}

// RMSNorm row + anw + SiLU(gate) -> o^T fp16 (hi only)
__global__ void rmsgate_kernel(const float* __restrict__ anw)
{
    __shared__ float red[4];
    int r = blockIdx.x;
    int t = threadIdx.x;
    int dg = t << 2;
    long long arow = (long long)r * DIM + dg;
    __half2 ah0 = *(const __half2*)(g_athi + arow);
    __half2 ah1 = *(const __half2*)(g_athi + arow + 2);
    __half2 al0 = *(const __half2*)(g_atlo + arow);
    __half2 al1 = *(const __half2*)(g_atlo + arow + 2);
    float a0 = __half2float(ah0.x) + __half2float(al0.x);
    float a1 = __half2float(ah0.y) + __half2float(al0.y);
    float a2 = __half2float(ah1.x) + __half2float(al1.x);
    float a3 = __half2float(ah1.y) + __half2float(al1.y);
    float ss = a0 * a0 + a1 * a1 + a2 * a2 + a3 * a3;
    int lane = t & 31, w = t >> 5;
#pragma unroll
    for (int off = 16; off > 0; off >>= 1)
        ss += __shfl_down_sync(0xffffffffu, ss, off);
    if (lane == 0) red[w] = ss;
    __syncthreads();
    float tot = red[0] + red[1] + red[2] + red[3];
    float rms = rsqrtf(tot * (1.f / DIM) + 1e-6f);

    long long grow = (long long)r * C4 + 1536 + dg;
    __half2 gh0 = *(const __half2*)(g_ythi + grow);
    __half2 gh1 = *(const __half2*)(g_ythi + grow + 2);
    float yg0 = __half2float(gh0.x);
    float yg1 = __half2float(gh0.y);
    float yg2 = __half2float(gh1.x);
    float yg3 = __half2float(gh1.y);
    float4 ga = *(const float4*)(g_a1 + 1536 + dg);
    float4 gb = *(const float4*)(g_b1 + 1536 + dg);
    float4 wn = *(const float4*)(anw + dg);
    float g0 = ga.x * yg0 + gb.x, g1 = ga.y * yg1 + gb.y;
    float g2 = ga.z * yg2 + gb.z, g3 = ga.w * yg3 + gb.w;
    float o0 = a0 * rms * wn.x * (g0 / (1.f + expf(-g0)));
    float o1 = a1 * rms * wn.y * (g1 / (1.f + expf(-g1)));
    float o2 = a2 * rms * wn.z * (g2 / (1.f + expf(-g2)));
    float o3 = a3 * rms * wn.w * (g3 / (1.f + expf(-g3)));
    long long o = (long long)r * DIM + dg;
    *(__half2*)(g_othi + o)     = h2_rn(o0, o1);
    *(__half2*)(g_othi + o + 2) = h2_rn(o2, o3);
}

// BN2 apply: out = a2*ypre(fp16) + b2, f32 out
__global__ void bnapply_kernel(float* __restrict__ out)
{
    long long i = (long long)(blockIdx.x * blockDim.x + threadIdx.x) * 4;
    int c = (int)((i >> 12) & 511);
    float a = g_a2[c], bb = g_b2[c];
    __half2 p0 = *(const __half2*)(g_ypreh + i);
    __half2 p1 = *(const __half2*)(g_ypreh + i + 2);
    float4 v;
    v.x = a * __half2float(p0.x) + bb;
    v.y = a * __half2float(p0.y) + bb;
    v.z = a * __half2float(p1.x) + bb;
    v.w = a * __half2float(p1.y) + bb;
    *reinterpret_cast<float4*>(out + i) = v;
}

// f32 -> fp16 (hi only)
__global__ void convert_half(const float* __restrict__ s,
                             __half* __restrict__ hi, int n)
{
    int i = blockIdx.x * blockDim.x + threadIdx.x;
    if (i < n) hi[i] = __float2half_rn(s[i]);
}

// transpose f32 src [b][R][Cc] -> fp16 hi-only dst [b][Cc][R]
__global__ void transpose_half(const float* __restrict__ src,
                               __half* __restrict__ dhi, int R, int Cc)
{
    __shared__ float t[32][33];
    int b = blockIdx.z;
    long long o = (long long)b * R * Cc;
    src += o; dhi += o;
    int c0 = blockIdx.x * 32, r0 = blockIdx.y * 32;
    int tx = threadIdx.x, ty = threadIdx.y;
#pragma unroll
    for (int i = 0; i < 4; i++)
        t[ty + 8 * i][tx] = src[(long long)(r0 + ty + 8 * i) * Cc + c0 + tx];
    __syncthreads();
#pragma unroll
    for (int i = 0; i < 4; i++) {
        int cc = c0 + ty + 8 * i;
        dhi[(long long)cc * R + r0 + tx] = __float2half_rn(t[tx][ty + 8 * i]);
    }
}

// ---------------------------------------------------------------------------
extern "C" void kernel_launch(void* const* d_in, const int* in_sizes, int n_in,
                              void* d_out, int out_size)
{
    const float* x           = (const float*)d_in[0];
    const float* qkvg_w      = (const float*)d_in[1];
    const float* qkvg_gamma  = (const float*)d_in[2];
    const float* qkvg_beta   = (const float*)d_in[3];
    const float* attn_norm_w = (const float*)d_in[4];
    const float* proj_w      = (const float*)d_in[5];
    const float* proj_gamma  = (const float*)d_in[6];
    const float* proj_beta   = (const float*)d_in[7];
    float* out = (float*)d_out;

    cudaFuncSetAttribute(gemm_mma<false, false, true, true, false>,
                         cudaFuncAttributeMaxDynamicSharedMemorySize, GSMEM);
    cudaFuncSetAttribute(gemm_mma<false, false, false, false, false>,
                         cudaFuncAttributeMaxDynamicSharedMemorySize, GSMEM);
    cudaFuncSetAttribute(gemm_mma<true, true, false, false, false>,
                         cudaFuncAttributeMaxDynamicSharedMemorySize, GSMEM);
    cudaFuncSetAttribute(gemm_mma<false, false, true, false, true>,
                         cudaFuncAttributeMaxDynamicSharedMemorySize, GSMEM);

    float *pvkp, *pz;
    __half *pythi, *pathi, *patlo, *pypreh;
    __half *pkhi, *pvhi, *pqthi, *pxthi, *pothi, *pvkhi, *pwqhi, *ppwhi;
    cudaGetSymbolAddress((void**)&pythi, g_ythi);
    cudaGetSymbolAddress((void**)&pathi, g_athi);
    cudaGetSymbolAddress((void**)&patlo, g_atlo);
    cudaGetSymbolAddress((void**)&pypreh, g_ypreh);
    cudaGetSymbolAddress((void**)&pvkp,  g_vkp);
    cudaGetSymbolAddress((void**)&pz,    g_z);
    cudaGetSymbolAddress((void**)&pkhi,  g_khi);
    cudaGetSymbolAddress((void**)&pvhi,  g_vhi);
    cudaGetSymbolAddress((void**)&pqthi, g_qthi);
    cudaGetSymbolAddress((void**)&pxthi, g_xthi);
    cudaGetSymbolAddress((void**)&pothi, g_othi);
    cudaGetSymbolAddress((void**)&pvkhi, g_vkhi);
    cudaGetSymbolAddress((void**)&pwqhi, g_wqhi);
    cudaGetSymbolAddress((void**)&ppwhi, g_pwhi);

    const long long sQKV = (long long)DIM * NPIX;   // 2097152
    const long long sYT  = (long long)NPIX * C4;    // 8388608
    const long long sVK  = (long long)DIM * DIM;    // 262144

    zero_kernel<<<32, 256>>>();
    convert_half<<<4096, 256>>>(qkvg_w, pwqhi, C4 * DIM);
    convert_half<<<1024, 256>>>(proj_w, ppwhi, DIM * DIM);
    transpose_half<<<dim3(128, 16, BATCH), dim3(32, 8)>>>(x, pxthi, DIM, NPIX);

    // 1) y^T = x^T @ w^T -> fp16 hi + fused BN1 column stats
    gemm_mma<false, false, true, true, false><<<dim3(16, 32, BATCH), 128, GSMEM>>>(
        pxthi, pwqhi, nullptr, pythi, nullptr,
        2048, 512, 512, 1, sQKV, 0, sYT, 1.f, nullptr);

    // 2) BN1 finalize
    bn1_finalize<<<8, 256>>>(qkvg_gamma, qkvg_beta);

    // 3) q^T fp16; k hi + v hi -> [d][n] + ksum
    q_kernel<<<16384, 256>>>();
    kvt_kernel<<<dim3(64, 8, BATCH), dim3(32, 8)>>>();

    // 4) z
    z_kernel<<<4096, 256>>>();

    // 5) vk = v @ k^T, split-K x4; reduce -> fp16 hi
    gemm_mma<false, false, false, false, false><<<dim3(4, 4, BATCH * 4), 128, GSMEM>>>(
        pvhi, pkhi, pvkp, nullptr, nullptr,
        512, 1024, 4096, 4, sQKV, sQKV, sVK, 1.f, nullptr);
    vkred_kernel<<<2048, 256>>>();

    // 6) attn^T = q^T @ vk^T / z -> hi/lo fp16
    gemm_mma<true, true, false, false, false><<<dim3(4, 32, BATCH), 128, GSMEM>>>(
        pqthi, pvkhi, nullptr, pathi, patlo,
        512, 512, 512, 1, sQKV, sVK, sQKV, 1.f, pz);

    // 7) RMSNorm + gate -> o^T fp16
    rmsgate_kernel<<<32768, 128>>>(attn_norm_w);

    // 8) ypre = proj_w @ o (fp16 out) + fused BN2 row stats
    gemm_mma<false, false, true, false, true><<<dim3(32, 4, BATCH), 128, GSMEM>>>(
        ppwhi, pothi, nullptr, pypreh, nullptr,
        4096, 512, 512, 1, 0, sQKV, sQKV, 1.f, nullptr);

    // 9) BN2 finalize + apply
    bn2_finalize<<<2, 256>>>(proj_gamma, proj_beta);
    bnapply_kernel<<<16384, 256>>>(out);
}

// round 17
// speedup vs baseline: 1.1297x; 1.0280x over previous
#include <cuda_runtime.h>
#include <cuda_fp16.h>
#include <math.h>
#include <stdint.h>

// ---------------------------------------------------------------------------
// SHMA block: pure fp16 mma.sync GEMMs (fp32 accum), BK=64, 2-stage
// cp.async pipeline, n-major dataflow, fused BN stats, wide (16B)
// elementwise kernels. B=8, dim=d=512, N=4096, qkvg=2048.
// ---------------------------------------------------------------------------

#define BATCH 8
#define DIM   512
#define NPIX  4096
#define C4    2048

// ---------------- scratch (static device globals) --------------------------
__device__ __half g_ythi[67108864];                   // y^T (8*4096,2048)
__device__ __half g_athi[16777216], g_atlo[16777216]; // attn^T (8*4096,512)
__device__ __half g_ypreh[16777216];                  // ypre (8, 512, 4096) fp16
__device__ float g_vkp[8388608];                      // vk split-K partials
__device__ __half g_khi[16777216];                    // k [b][d][n]
__device__ __half g_vhi[16777216];                    // v [b][d][n]
__device__ __half g_qthi[16777216];                   // q^T [b][n][d]
__device__ __half g_xthi[16777216];                   // x^T [b][n][c]
__device__ __half g_othi[16777216];                   // o^T [b][n][d]
__device__ __half g_vkhi[2097152];                    // vk [b][d][e]
__device__ __half g_wqhi[1048576];                    // qkvg_w
__device__ __half g_pwhi[262144];                     // proj_w
__device__ float g_a1[2048], g_b1[2048], g_a2[512], g_b2[512];
__device__ float g_s1[2048], g_s2[2048];              // BN1 accum
__device__ float g_t1[512], g_t2[512];                // BN2 accum
__device__ float g_ksum[4096], g_z[32768];

// ---------------- helpers ---------------------------------------------------
__device__ __forceinline__ uint32_t smem_u32(const void* p) {
    uint32_t a;
    asm("{ .reg .u64 t; cvta.to.shared.u64 t, %1; cvt.u32.u64 %0, t; }"
        : "=r"(a) : "l"(p));
    return a;
}
__device__ __forceinline__ void ldsm_x4(uint32_t& r0, uint32_t& r1,
                                        uint32_t& r2, uint32_t& r3,
                                        uint32_t addr) {
    asm volatile("ldmatrix.sync.aligned.m8n8.x4.shared.b16 {%0,%1,%2,%3}, [%4];"
                 : "=r"(r0), "=r"(r1), "=r"(r2), "=r"(r3) : "r"(addr));
}
__device__ __forceinline__ void mma16816(float* c, const uint32_t* a,
                                         uint32_t b0, uint32_t b1) {
    asm volatile(
        "mma.sync.aligned.m16n8k16.row.col.f32.f16.f16.f32 "
        "{%0,%1,%2,%3}, {%4,%5,%6,%7}, {%8,%9}, {%0,%1,%2,%3};"
        : "+f"(c[0]), "+f"(c[1]), "+f"(c[2]), "+f"(c[3])
        : "r"(a[0]), "r"(a[1]), "r"(a[2]), "r"(a[3]), "r"(b0), "r"(b1));
}
__device__ __forceinline__ void cpasync16(uint32_t dst, const void* src) {
    asm volatile("cp.async.cg.shared.global [%0], [%1], 16;"
                 :: "r"(dst), "l"(src));
}
#define CP_COMMIT() asm volatile("cp.async.commit_group;" ::: "memory")
#define CP_WAIT(n)  asm volatile("cp.async.wait_group %0;" :: "n"(n) : "memory")

__device__ __forceinline__ __half2 splith2(float a, float b, __half2& lo) {
    __half h0 = __float2half_rn(a), h1 = __float2half_rn(b);
    lo = __halves2half2(__float2half_rn(a - __half2float(h0)),
                        __float2half_rn(b - __half2float(h1)));
    return __halves2half2(h0, h1);
}
__device__ __forceinline__ __half2 h2_rn(float a, float b) {
    return __halves2half2(__float2half_rn(a), __float2half_rn(b));
}
__device__ __forceinline__ float sigm(float x) {
    return 1.f / (1.f + expf(-x));
}

// ---------------------------------------------------------------------------
// mma.sync fp16 GEMM: C = alpha * A @ B^T (fp32 accum).
//   128x128 CTA tile, BK=64, 128 threads (2x2 warps, 64x64 warp tiles),
//   2-stage cp.async double buffer, padded smem (SROW=72: 144B rows).
//   Split-K via blockIdx.z = b*kchunks + ks (f32 C offset by zi*sC).
//   ZDIV: row-divide by zb. OUTSPLIT: hi/lo fp16 out. OUTH: fp16 hi out.
//   STATS: per-column sum/sumsq atomics. ROWSTATS: per-row sum/sumsq atomics.
// ---------------------------------------------------------------------------
#define SROW 72
#define BUFB (128u * SROW * 2u)
#define GSMEM (2 * 2 * BUFB + 512)

template <bool ZDIV, bool OUTSPLIT, bool OUTH, bool STATS, bool ROWSTATS>
__global__ void __launch_bounds__(128)
gemm_mma(const __half* __restrict__ A_, const __half* __restrict__ B_,
         float* __restrict__ C_, __half* __restrict__ Chi_,
         __half* __restrict__ Clo_,
         int N, int K, int ldk, int kchunks,
         long long sA, long long sB, long long sC,
         float alpha, const float* __restrict__ zb)
{
    extern __shared__ char smem[];
    const int zi = blockIdx.z;
    const int b  = zi / kchunks;
    const int ks = zi - b * kchunks;
    const long long koff = (long long)ks * K;

    const __half* A = A_ + (long long)b * sA + koff;
    const __half* B = B_ + (long long)b * sB + koff;
    const int m0 = blockIdx.y << 7, n0 = blockIdx.x << 7;
    const int tid = threadIdx.x, wid = tid >> 5, lane = tid & 31;
    const int wm = wid & 1, wn = wid >> 1;
    const int tig = lane & 3, grp = lane >> 2;

    const uint32_t sb = smem_u32(smem);
    float* zsm = (float*)(smem + 4 * BUFB);
    if (ZDIV) zsm[tid] = 1.f / zb[(long long)b * 4096 + m0 + tid];

    const int CH = K >> 6;

    float acc[4][8][4];
#pragma unroll
    for (int i = 0; i < 4; i++)
#pragma unroll
        for (int j = 0; j < 8; j++)
#pragma unroll
            for (int t = 0; t < 4; t++) acc[i][j][t] = 0.f;

    auto load = [&](int c, int st) {
        long long kp = (long long)c << 6;
        uint32_t base = sb + (uint32_t)st * (2u * BUFB);
#pragma unroll
        for (int i = 0; i < 8; i++) {
            int slot = tid + (i << 7);
            int row = slot >> 3, u = slot & 7;
            uint32_t d = (uint32_t)(row * (SROW * 2) + (u << 4));
            cpasync16(base + d, A + (long long)(m0 + row) * ldk + kp + (u << 3));
            cpasync16(base + BUFB + d,
                      B + (long long)(n0 + row) * ldk + kp + (u << 3));
        }
        CP_COMMIT();
    };

    load(0, 0);

    const uint32_t lrow16 = lane & 15;
    const uint32_t lcol8 = (lane >> 4) << 3;

    int buf = 0;
    for (int c = 0; c < CH; c++) {
        if (c + 1 < CH) { load(c + 1, buf ^ 1); CP_WAIT(1); }
        else            { CP_WAIT(0); }
        __syncthreads();

        uint32_t base = sb + (uint32_t)buf * (2u * BUFB);
#pragma unroll
        for (int ko2 = 0; ko2 < 4; ko2++) {
            const uint32_t ko = ko2 << 4;
            uint32_t a[4][4], bb[4][4];
#pragma unroll
            for (int mi = 0; mi < 4; mi++) {
                uint32_t ad = base +
                    (((wm << 6) + (mi << 4) + lrow16) * SROW + ko + lcol8) * 2;
                ldsm_x4(a[mi][0], a[mi][1], a[mi][2], a[mi][3], ad);
            }
#pragma unroll
            for (int nb = 0; nb < 4; nb++) {
                uint32_t bd = base + BUFB +
                    (((wn << 6) + (nb << 4) + lrow16) * SROW + ko + lcol8) * 2;
                ldsm_x4(bb[nb][0], bb[nb][1], bb[nb][2], bb[nb][3], bd);
            }
#pragma unroll
            for (int mi = 0; mi < 4; mi++)
#pragma unroll
                for (int ni = 0; ni < 8; ni++) {
                    int nb = ni >> 1, hf = ni & 1;
                    mma16816(acc[mi][ni], a[mi], bb[nb][hf], bb[nb][hf + 2]);
                }
        }
        __syncthreads();
        buf ^= 1;
    }

    // epilogue
    float* C = C_ + (long long)zi * sC;
    __half* Chi = Chi_ + (long long)b * sC;
    __half* Clo = Clo_ + (long long)b * sC;
    float cs1[8][2], cs2[8][2];
    float rs1[4][2], rs2[4][2];
    if (STATS) {
#pragma unroll
        for (int ni = 0; ni < 8; ni++) {
            cs1[ni][0] = cs1[ni][1] = 0.f;
            cs2[ni][0] = cs2[ni][1] = 0.f;
        }
    }
    if (ROWSTATS) {
#pragma unroll
        for (int mi = 0; mi < 4; mi++) {
            rs1[mi][0] = rs1[mi][1] = 0.f;
            rs2[mi][0] = rs2[mi][1] = 0.f;
        }
    }
#pragma unroll
    for (int mi = 0; mi < 4; mi++) {
        int rl = (wm << 6) + (mi << 4) + grp;
        int row = m0 + rl;
        float zr0 = 1.f, zr1 = 1.f;
        if (ZDIV) { zr0 = zsm[rl]; zr1 = zsm[rl + 8]; }
#pragma unroll
        for (int ni = 0; ni < 8; ni++) {
            int col = n0 + (wn << 6) + (ni << 3) + (tig << 1);
            float v0 = acc[mi][ni][0] * alpha;
            float v1 = acc[mi][ni][1] * alpha;
            float v2 = acc[mi][ni][2] * alpha;
            float v3 = acc[mi][ni][3] * alpha;
            if (ZDIV) { v0 *= zr0; v1 *= zr0; v2 *= zr1; v3 *= zr1; }
            if (STATS) {
                cs1[ni][0] += v0 + v2;
                cs1[ni][1] += v1 + v3;
                cs2[ni][0] += v0 * v0 + v2 * v2;
                cs2[ni][1] += v1 * v1 + v3 * v3;
            }
            if (ROWSTATS) {
                rs1[mi][0] += v0 + v1;
                rs2[mi][0] += v0 * v0 + v1 * v1;
                rs1[mi][1] += v2 + v3;
                rs2[mi][1] += v2 * v2 + v3 * v3;
            }
            if (OUTSPLIT) {
                __half2 l0, l1;
                __half2 h0 = splith2(v0, v1, l0);
                __half2 h1 = splith2(v2, v3, l1);
                *(__half2*)(Chi + (long long)row * N + col) = h0;
                *(__half2*)(Chi + (long long)(row + 8) * N + col) = h1;
                *(__half2*)(Clo + (long long)row * N + col) = l0;
                *(__half2*)(Clo + (long long)(row + 8) * N + col) = l1;
            } else if (OUTH) {
                *(__half2*)(Chi + (long long)row * N + col) = h2_rn(v0, v1);
                *(__half2*)(Chi + (long long)(row + 8) * N + col) = h2_rn(v2, v3);
            } else {
                float2 p0; p0.x = v0; p0.y = v1;
                float2 p1; p1.x = v2; p1.y = v3;
                *(float2*)(C + (long long)row * N + col) = p0;
                *(float2*)(C + (long long)(row + 8) * N + col) = p1;
            }
        }
    }
    if (STATS) {
#pragma unroll
        for (int ni = 0; ni < 8; ni++)
#pragma unroll
            for (int h = 0; h < 2; h++) {
                float s1 = cs1[ni][h], s2 = cs2[ni][h];
                s1 += __shfl_down_sync(0xffffffffu, s1, 16);
                s2 += __shfl_down_sync(0xffffffffu, s2, 16);
                s1 += __shfl_down_sync(0xffffffffu, s1, 8);
                s2 += __shfl_down_sync(0xffffffffu, s2, 8);
                s1 += __shfl_down_sync(0xffffffffu, s1, 4);
                s2 += __shfl_down_sync(0xffffffffu, s2, 4);
                if (lane < 4) {
                    int col = n0 + (wn << 6) + (ni << 3) + (lane << 1) + h;
                    atomicAdd(&g_s1[col], s1);
                    atomicAdd(&g_s2[col], s2);
                }
            }
    }
    if (ROWSTATS) {
#pragma unroll
        for (int mi = 0; mi < 4; mi++)
#pragma unroll
            for (int h = 0; h < 2; h++) {
                float s1 = rs1[mi][h], s2 = rs2[mi][h];
                s1 += __shfl_down_sync(0xffffffffu, s1, 2, 4);
                s2 += __shfl_down_sync(0xffffffffu, s2, 2, 4);
                s1 += __shfl_down_sync(0xffffffffu, s1, 1, 4);
                s2 += __shfl_down_sync(0xffffffffu, s2, 1, 4);
                if (tig == 0) {
                    int row = m0 + (wm << 6) + (mi << 4) + grp + (h << 3);
                    atomicAdd(&g_t1[row], s1);
                    atomicAdd(&g_t2[row], s2);
                }
            }
    }
}

// ---------------------------------------------------------------------------
// vk split-K reduce -> fp16 (hi only); 8B store
// ---------------------------------------------------------------------------
__global__ void vkred_kernel()
{
    long long i4 = (long long)(blockIdx.x * 256 + threadIdx.x) * 4;
    int b = (int)(i4 >> 18);
    long long off = i4 & 262143;
    const float* p = g_vkp + ((long long)b * 4) * 262144 + off;
    float4 s0 = *(const float4*)p;
    float4 s1 = *(const float4*)(p + 262144);
    float4 s2 = *(const float4*)(p + 2 * 262144);
    float4 s3 = *(const float4*)(p + 3 * 262144);
    const float al = 1.f / 4096.f;
    float v0 = ((s0.x + s1.x) + (s2.x + s3.x)) * al;
    float v1 = ((s0.y + s1.y) + (s2.y + s3.y)) * al;
    float v2 = ((s0.z + s1.z) + (s2.z + s3.z)) * al;
    float v3 = ((s0.w + s1.w) + (s2.w + s3.w)) * al;
    __half2 o[2];
    o[0] = h2_rn(v0, v1);
    o[1] = h2_rn(v2, v3);
    *(uint2*)(g_vkhi + i4) = *(uint2*)o;
}

// ---------------------------------------------------------------------------
__global__ void zero_kernel()
{
    int i = blockIdx.x * 256 + threadIdx.x;
    if (i < 2048) { g_s1[i] = 0.f; g_s2[i] = 0.f; }
    if (i < 512)  { g_t1[i] = 0.f; g_t2[i] = 0.f; }
    if (i < 4096) g_ksum[i] = 0.f;
}

__global__ void bn1_finalize(const float* __restrict__ gamma,
                             const float* __restrict__ beta)
{
    int c = blockIdx.x * 256 + threadIdx.x;
    const float inv = 1.f / (BATCH * NPIX);
    float mean = g_s1[c] * inv;
    float var = g_s2[c] * inv - mean * mean;
    float av = gamma[c] * rsqrtf(var + 1e-5f);
    g_a1[c] = av;
    g_b1[c] = beta[c] - mean * av;
}

__global__ void bn2_finalize(const float* __restrict__ gamma,
                             const float* __restrict__ beta)
{
    int c = blockIdx.x * 256 + threadIdx.x;
    const float inv = 1.f / (BATCH * NPIX);
    float mean = g_t1[c] * inv;
    float var = g_t2[c] * inv - mean * mean;
    float av = gamma[c] * rsqrtf(var + 1e-5f);
    g_a2[c] = av;
    g_b2[c] = beta[c] - mean * av;
}

// q: 8 elems/thread; sigmoid(affine(y[:,0:512])) -> q^T fp16
__global__ void q_kernel()
{
    int i = blockIdx.x * 256 + threadIdx.x;     // 2.097M threads
    int r = i >> 6;                              // 64 threads per row
    int dg = (i & 63) << 3;                      // 8 d's per thread
    __half yv[8];
    *(uint4*)yv = *(const uint4*)(g_ythi + (long long)r * C4 + dg);
    float4 a0 = *(const float4*)(g_a1 + dg);
    float4 a1 = *(const float4*)(g_a1 + dg + 4);
    float4 b0 = *(const float4*)(g_b1 + dg);
    float4 b1 = *(const float4*)(g_b1 + dg + 4);
    float av[8] = {a0.x, a0.y, a0.z, a0.w, a1.x, a1.y, a1.z, a1.w};
    float bv[8] = {b0.x, b0.y, b0.z, b0.w, b1.x, b1.y, b1.z, b1.w};
    __half qv[8];
#pragma unroll
    for (int j = 0; j < 8; j++)
        qv[j] = __float2half_rn(sigm(av[j] * __half2float(yv[j]) + bv[j]));
    *(uint4*)(g_qthi + (long long)r * DIM + dg) = *(uint4*)qv;
}

// k,v: 64x64 tile transpose, 16B global accesses, ksum. 256 threads flat.
__global__ void kvt_kernel()
{
    __shared__ float tk[64][65], tv[64][65];
    int bz = blockIdx.z;
    int n0 = blockIdx.x << 6, d0 = blockIdx.y << 6;
    int tid = threadIdx.x;

    // phase 1: load 64 n-rows x 64 d (k and v channels), activate, stage
#pragma unroll
    for (int it = 0; it < 2; it++) {
        int slot = tid + (it << 8);
        int nl = slot >> 3, u = slot & 7;       // row, 8-d chunk
        int db = u << 3;
        long long rb = ((long long)(bz << 12) + n0 + nl) * C4;
        __half kv8[8], vv8[8];
        *(uint4*)kv8 = *(const uint4*)(g_ythi + rb + 512 + d0 + db);
        *(uint4*)vv8 = *(const uint4*)(g_ythi + rb + 1024 + d0 + db);
        float4 ka0 = *(const float4*)(g_a1 + 512 + d0 + db);
        float4 ka1 = *(const float4*)(g_a1 + 512 + d0 + db + 4);
        float4 kb0 = *(const float4*)(g_b1 + 512 + d0 + db);
        float4 kb1 = *(const float4*)(g_b1 + 512 + d0 + db + 4);
        float4 va0 = *(const float4*)(g_a1 + 1024 + d0 + db);
        float4 va1 = *(const float4*)(g_a1 + 1024 + d0 + db + 4);
        float4 vb0 = *(const float4*)(g_b1 + 1024 + d0 + db);
        float4 vb1 = *(const float4*)(g_b1 + 1024 + d0 + db + 4);
        float ka[8] = {ka0.x, ka0.y, ka0.z, ka0.w, ka1.x, ka1.y, ka1.z, ka1.w};
        float kb[8] = {kb0.x, kb0.y, kb0.z, kb0.w, kb1.x, kb1.y, kb1.z, kb1.w};
        float va[8] = {va0.x, va0.y, va0.z, va0.w, va1.x, va1.y, va1.z, va1.w};
        float vb[8] = {vb0.x, vb0.y, vb0.z, vb0.w, vb1.x, vb1.y, vb1.z, vb1.w};
#pragma unroll
        for (int j = 0; j < 8; j++) {
            tk[nl][db + j] = sigm(ka[j] * __half2float(kv8[j]) + kb[j]);
            tv[nl][db + j] = va[j] * __half2float(vv8[j]) + vb[j];
        }
    }
    __syncthreads();

    // phase 2: write 64 d-rows x 64 n, 16B stores; ksum per d
#pragma unroll
    for (int it = 0; it < 2; it++) {
        int slot = tid + (it << 8);
        int dl = slot >> 3, un = slot & 7;      // d-row, 8-n chunk
        int nb = un << 3;
        __half ko[8], vo[8];
        float s = 0.f;
#pragma unroll
        for (int j = 0; j < 8; j++) {
            float kf = tk[nb + j][dl];
            float vf = tv[nb + j][dl];
            ko[j] = __float2half_rn(kf);
            vo[j] = __float2half_rn(vf);
            s += kf;
        }
        long long o = ((long long)(bz << 9) + d0 + dl) * NPIX + n0 + nb;
        *(uint4*)(g_khi + o) = *(uint4*)ko;
        *(uint4*)(g_vhi + o) = *(uint4*)vo;
        s += __shfl_down_sync(0xffffffffu, s, 4, 8);
        s += __shfl_down_sync(0xffffffffu, s, 2, 8);
        s += __shfl_down_sync(0xffffffffu, s, 1, 8);
        if (un == 0) atomicAdd(&g_ksum[(bz << 9) + d0 + dl], s);
    }
}

// z[r] = sum_d kmean[d] * q[r][d] + eps
__global__ void z_kernel()
{
    __shared__ float km[512];
    int r0 = blockIdx.x << 3;
    int bb = r0 >> 12;
    for (int i = threadIdx.x; i < 512; i += 256)
        km[i] = g_ksum[(bb << 9) + i] * (1.f / NPIX);
    __syncthreads();
    int w = threadIdx.x >> 5, lane = threadIdx.x & 31;
    int r = r0 + w;
    const __half* qh = g_qthi + (long long)r * DIM;
    float s = 0.f;
#pragma unroll
    for (int i = 0; i < 16; i++) {
        int d = lane + (i << 5);
        s += km[d] * __half2float(qh[d]);
    }
#pragma unroll
    for (int off = 16; off > 0; off >>= 1)
        s += __shfl_down_sync(0xffffffffu, s, off);
    if (lane == 0) g_z[r] = s + 5e-4f;
}

// RMSNorm + anw + SiLU(gate) -> o^T fp16. 8 elems/thread, 2 rows per block.
__global__ void rmsgate_kernel(const float* __restrict__ anw)
{
    __shared__ float red[2][2];
    int tid = threadIdx.x;
    int rloc = tid >> 6;                 // 0/1: row within block
    int t6 = tid & 63;
    int r = (blockIdx.x << 1) + rloc;
    int dg = t6 << 3;
    long long arow = (long long)r * DIM + dg;
    __half ah[8], al[8];
    *(uint4*)ah = *(const uint4*)(g_athi + arow);
    *(uint4*)al = *(const uint4*)(g_atlo + arow);
    float a[8];
    float ss = 0.f;
#pragma unroll
    for (int j = 0; j < 8; j++) {
        a[j] = __half2float(ah[j]) + __half2float(al[j]);
        ss += a[j] * a[j];
    }
    int lane = tid & 31;
#pragma unroll
    for (int off = 16; off > 0; off >>= 1)
        ss += __shfl_down_sync(0xffffffffu, ss, off);
    if (lane == 0) red[rloc][(t6 >> 5)] = ss;
    __syncthreads();
    float rms = rsqrtf((red[rloc][0] + red[rloc][1]) * (1.f / DIM) + 1e-6f);

    __half gh[8];
    *(uint4*)gh = *(const uint4*)(g_ythi + (long long)r * C4 + 1536 + dg);
    float4 ga0 = *(const float4*)(g_a1 + 1536 + dg);
    float4 ga1 = *(const float4*)(g_a1 + 1536 + dg + 4);
    float4 gb0 = *(const float4*)(g_b1 + 1536 + dg);
    float4 gb1 = *(const float4*)(g_b1 + 1536 + dg + 4);
    float4 wn0 = *(const float4*)(anw + dg);
    float4 wn1 = *(const float4*)(anw + dg + 4);
    float ga[8] = {ga0.x, ga0.y, ga0.z, ga0.w, ga1.x, ga1.y, ga1.z, ga1.w};
    float gb[8] = {gb0.x, gb0.y, gb0.z, gb0.w, gb1.x, gb1.y, gb1.z, gb1.w};
    float wn[8] = {wn0.x, wn0.y, wn0.z, wn0.w, wn1.x, wn1.y, wn1.z, wn1.w};
    __half oo[8];
#pragma unroll
    for (int j = 0; j < 8; j++) {
        float g = ga[j] * __half2float(gh[j]) + gb[j];
        float sg = g * sigm(g);
        oo[j] = __float2half_rn(a[j] * rms * wn[j] * sg);
    }
    *(uint4*)(g_othi + (long long)r * DIM + dg) = *(uint4*)oo;
}

// BN2 apply: 8 elems/thread; out = a2*ypre(fp16) + b2
__global__ void bnapply_kernel(float* __restrict__ out)
{
    long long i8 = (long long)(blockIdx.x * 256 + threadIdx.x) * 8;
    int c = (int)((i8 >> 12) & 511);
    float a = g_a2[c], bb = g_b2[c];
    __half p[8];
    *(uint4*)p = *(const uint4*)(g_ypreh + i8);
    float4 v0, v1;
    v0.x = a * __half2float(p[0]) + bb;
    v0.y = a * __half2float(p[1]) + bb;
    v0.z = a * __half2float(p[2]) + bb;
    v0.w = a * __half2float(p[3]) + bb;
    v1.x = a * __half2float(p[4]) + bb;
    v1.y = a * __half2float(p[5]) + bb;
    v1.z = a * __half2float(p[6]) + bb;
    v1.w = a * __half2float(p[7]) + bb;
    *reinterpret_cast<float4*>(out + i8)     = v0;
    *reinterpret_cast<float4*>(out + i8 + 4) = v1;
}

// f32 -> fp16 (hi only)
__global__ void convert_half(const float* __restrict__ s,
                             __half* __restrict__ hi, int n)
{
    int i = blockIdx.x * blockDim.x + threadIdx.x;
    if (i < n) hi[i] = __float2half_rn(s[i]);
}

// transpose f32 src [b][R][Cc] -> fp16 hi-only dst [b][Cc][R]
__global__ void transpose_half(const float* __restrict__ src,
                               __half* __restrict__ dhi, int R, int Cc)
{
    __shared__ float t[32][33];
    int b = blockIdx.z;
    long long o = (long long)b * R * Cc;
    src += o; dhi += o;
    int c0 = blockIdx.x * 32, r0 = blockIdx.y * 32;
    int tx = threadIdx.x, ty = threadIdx.y;
#pragma unroll
    for (int i = 0; i < 4; i++)
        t[ty + 8 * i][tx] = src[(long long)(r0 + ty + 8 * i) * Cc + c0 + tx];
    __syncthreads();
#pragma unroll
    for (int i = 0; i < 4; i++) {
        int cc = c0 + ty + 8 * i;
        dhi[(long long)cc * R + r0 + tx] = __float2half_rn(t[tx][ty + 8 * i]);
    }
}

// ---------------------------------------------------------------------------
extern "C" void kernel_launch(void* const* d_in, const int* in_sizes, int n_in,
                              void* d_out, int out_size)
{
    const float* x           = (const float*)d_in[0];
    const float* qkvg_w      = (const float*)d_in[1];
    const float* qkvg_gamma  = (const float*)d_in[2];
    const float* qkvg_beta   = (const float*)d_in[3];
    const float* attn_norm_w = (const float*)d_in[4];
    const float* proj_w      = (const float*)d_in[5];
    const float* proj_gamma  = (const float*)d_in[6];
    const float* proj_beta   = (const float*)d_in[7];
    float* out = (float*)d_out;

    cudaFuncSetAttribute(gemm_mma<false, false, true, true, false>,
                         cudaFuncAttributeMaxDynamicSharedMemorySize, GSMEM);
    cudaFuncSetAttribute(gemm_mma<false, false, false, false, false>,
                         cudaFuncAttributeMaxDynamicSharedMemorySize, GSMEM);
    cudaFuncSetAttribute(gemm_mma<true, true, false, false, false>,
                         cudaFuncAttributeMaxDynamicSharedMemorySize, GSMEM);
    cudaFuncSetAttribute(gemm_mma<false, false, true, false, true>,
                         cudaFuncAttributeMaxDynamicSharedMemorySize, GSMEM);

    float *pvkp, *pz;
    __half *pythi, *pathi, *patlo, *pypreh;
    __half *pkhi, *pvhi, *pqthi, *pxthi, *pothi, *pvkhi, *pwqhi, *ppwhi;
    cudaGetSymbolAddress((void**)&pythi, g_ythi);
    cudaGetSymbolAddress((void**)&pathi, g_athi);
    cudaGetSymbolAddress((void**)&patlo, g_atlo);
    cudaGetSymbolAddress((void**)&pypreh, g_ypreh);
    cudaGetSymbolAddress((void**)&pvkp,  g_vkp);
    cudaGetSymbolAddress((void**)&pz,    g_z);
    cudaGetSymbolAddress((void**)&pkhi,  g_khi);
    cudaGetSymbolAddress((void**)&pvhi,  g_vhi);
    cudaGetSymbolAddress((void**)&pqthi, g_qthi);
    cudaGetSymbolAddress((void**)&pxthi, g_xthi);
    cudaGetSymbolAddress((void**)&pothi, g_othi);
    cudaGetSymbolAddress((void**)&pvkhi, g_vkhi);
    cudaGetSymbolAddress((void**)&pwqhi, g_wqhi);
    cudaGetSymbolAddress((void**)&ppwhi, g_pwhi);

    const long long sQKV = (long long)DIM * NPIX;   // 2097152
    const long long sYT  = (long long)NPIX * C4;    // 8388608
    const long long sVK  = (long long)DIM * DIM;    // 262144

    zero_kernel<<<32, 256>>>();
    convert_half<<<4096, 256>>>(qkvg_w, pwqhi, C4 * DIM);
    convert_half<<<1024, 256>>>(proj_w, ppwhi, DIM * DIM);
    transpose_half<<<dim3(128, 16, BATCH), dim3(32, 8)>>>(x, pxthi, DIM, NPIX);

    // 1) y^T = x^T @ w^T -> fp16 hi + fused BN1 column stats
    gemm_mma<false, false, true, true, false><<<dim3(16, 32, BATCH), 128, GSMEM>>>(
        pxthi, pwqhi, nullptr, pythi, nullptr,
        2048, 512, 512, 1, sQKV, 0, sYT, 1.f, nullptr);

    // 2) BN1 finalize
    bn1_finalize<<<8, 256>>>(qkvg_gamma, qkvg_beta);

    // 3) q^T fp16; k hi + v hi -> [d][n] + ksum
    q_kernel<<<8192, 256>>>();
    kvt_kernel<<<dim3(64, 8, BATCH), 256>>>();

    // 4) z
    z_kernel<<<4096, 256>>>();

    // 5) vk = v @ k^T, split-K x4; reduce -> fp16 hi
    gemm_mma<false, false, false, false, false><<<dim3(4, 4, BATCH * 4), 128, GSMEM>>>(
        pvhi, pkhi, pvkp, nullptr, nullptr,
        512, 1024, 4096, 4, sQKV, sQKV, sVK, 1.f, nullptr);
    vkred_kernel<<<2048, 256>>>();

    // 6) attn^T = q^T @ vk^T / z -> hi/lo fp16
    gemm_mma<true, true, false, false, false><<<dim3(4, 32, BATCH), 128, GSMEM>>>(
        pqthi, pvkhi, nullptr, pathi, patlo,
        512, 512, 512, 1, sQKV, sVK, sQKV, 1.f, pz);

    // 7) RMSNorm + gate -> o^T fp16 (2 rows per block)
    rmsgate_kernel<<<16384, 128>>>(attn_norm_w);

    // 8) ypre = proj_w @ o (fp16 out) + fused BN2 row stats
    gemm_mma<false, false, true, false, true><<<dim3(32, 4, BATCH), 128, GSMEM>>>(
        ppwhi, pothi, nullptr, pypreh, nullptr,
        4096, 512, 512, 1, 0, sQKV, sQKV, 1.f, nullptr);

    // 9) BN2 finalize + apply
    bn2_finalize<<<2, 256>>>(proj_gamma, proj_beta);
    bnapply_kernel<<<8192, 256>>>(out);
}